// round 4
// baseline (speedup 1.0000x reference)
#include <cuda_runtime.h>
#include <cuda_bf16.h>
#include <cstdint>
#include <math.h>

#define H1 56
#define W1 56
#define BB 16
#define NN 32
#define CC 512
#define RH 60
#define RW 60
#define OH 224
#define OW 224
#define KS 33
#define KC 64
#define APITCH 72   // bf16 elements per smem row (64 data + 8 pad) ; 144 B

// ---------------- scratch (device globals; no allocation allowed) ----------
__device__ __nv_bfloat16 g_Eb[H1 * W1 * BB * CC];     // 51.4 MB
__device__ __nv_bfloat16 g_Mb[RH * RW * NN * CC];     // 118 MB
__device__ float g_xn[H1 * W1 * BB];
__device__ float g_yn[RH * RW * NN];
__device__ float g_best[H1 * W1 * BB];                // min dsq, via atomicMin(int)
__device__ float g_pix56[BB * H1 * W1];
__device__ float g_pix224[BB * OH * OW];
__device__ float g_tmp224[BB * OH * OW];
__device__ float g_gw[KS];

// ---------------- init: best=+inf, gaussian weights ------------------------
__global__ void k_init() {
    int i = blockIdx.x * blockDim.x + threadIdx.x;
    if (i < H1 * W1 * BB) g_best[i] = __int_as_float(0x7f800000);
    if (i < KS) {
        float s = 0.f;
        for (int t = 0; t < KS; t++) {
            float x = (t - (KS - 1) / 2) * 0.25f;   // /sigma=4
            s += expf(-0.5f * x * x);
        }
        float x = (i - (KS - 1) / 2) * 0.25f;
        g_gw[i] = expf(-0.5f * x * x) / s;
    }
}

// ---------------- fp32 -> bf16 conversion + row norms ----------------------
__device__ __forceinline__ void convert_row(const float* __restrict__ src,
                                            __nv_bfloat16* dst, float* norm,
                                            int row, int lane) {
    const float4* s = (const float4*)(src + (size_t)row * CC);
    uint2* d = (uint2*)(dst + (size_t)row * CC);
    float acc = 0.f;
#pragma unroll
    for (int it = 0; it < 4; it++) {
        float4 v = s[it * 32 + lane];
        acc += v.x * v.x + v.y * v.y + v.z * v.z + v.w * v.w;
        __nv_bfloat162 lo = __floats2bfloat162_rn(v.x, v.y);
        __nv_bfloat162 hi = __floats2bfloat162_rn(v.z, v.w);
        uint2 o;
        o.x = *(uint32_t*)&lo;
        o.y = *(uint32_t*)&hi;
        d[it * 32 + lane] = o;
    }
#pragma unroll
    for (int off = 16; off; off >>= 1) acc += __shfl_xor_sync(~0u, acc, off);
    if (lane == 0) norm[row] = acc;
}

__global__ void k_convert_e(const float* __restrict__ src) {
    int gw = (blockIdx.x * blockDim.x + threadIdx.x) >> 5;
    int lane = threadIdx.x & 31;
    if (gw < H1 * W1 * BB) convert_row(src, g_Eb, g_xn, gw, lane);
}
__global__ void k_convert_m(const float* __restrict__ src) {
    int gw = (blockIdx.x * blockDim.x + threadIdx.x) >> 5;
    int lane = threadIdx.x & 31;
    if (gw < RH * RW * NN) convert_row(src, g_Mb, g_yn, gw, lane);
}

// ---------------- main distance kernel: one CTA per memory tile ------------
__device__ __forceinline__ void mma16816(float* d, uint32_t a0, uint32_t a1,
                                         uint32_t a2, uint32_t a3,
                                         uint32_t b0, uint32_t b1) {
    asm volatile(
        "mma.sync.aligned.m16n8k16.row.col.f32.bf16.bf16.f32 "
        "{%0,%1,%2,%3}, {%4,%5,%6,%7}, {%8,%9}, {%0,%1,%2,%3};\n"
        : "+f"(d[0]), "+f"(d[1]), "+f"(d[2]), "+f"(d[3])
        : "r"(a0), "r"(a1), "r"(a2), "r"(a3), "r"(b0), "r"(b1));
}

__device__ __forceinline__ void ldsm_x4(uint32_t& r0, uint32_t& r1,
                                        uint32_t& r2, uint32_t& r3, uint32_t addr) {
    asm volatile("ldmatrix.sync.aligned.m8n8.x4.shared.b16 {%0,%1,%2,%3}, [%4];"
                 : "=r"(r0), "=r"(r1), "=r"(r2), "=r"(r3) : "r"(addr));
}

__device__ __forceinline__ void cp_async16(uint32_t dst, const void* src) {
    asm volatile("cp.async.cg.shared.global [%0], [%1], 16;" ::"r"(dst), "l"(src));
}

// smem layout (bytes):
//   A_s : 2 stages x 400*72*2 = 115200
//   B_s : 2 stages x 32*72*2  = 9216
//   xn_s: 400*4 = 1600 ; yn_s: 128 ; qoff: 100
#define A_STAGE_B 57600
#define B_STAGE_B 4608
#define SM_A   0
#define SM_B   115200
#define SM_XN  124416
#define SM_YN  126016
#define SM_Q   126144
#define SM_TOT 126272

#define NWARP 8
#define NTHR  256

__global__ void __launch_bounds__(NTHR, 1) k_dist() {
    extern __shared__ char smem[];
    float* xn_s = (float*)(smem + SM_XN);
    float* yn_s = (float*)(smem + SM_YN);
    int* qoff_s = (int*)(smem + SM_Q);
    const uint32_t sm_u32 = (uint32_t)__cvta_generic_to_shared(smem);
    const uint32_t smA_u32 = sm_u32 + SM_A;
    const uint32_t smB_u32 = sm_u32 + SM_B;

    const int tile = blockIdx.x;
    const int r = tile / RW, s = tile % RW;
    const int tid = threadIdx.x;
    const int wid = tid >> 5, lane = tid & 31;

    if (tid < 25) {
        int h = r - 4 + tid / 5, w = s - 4 + tid % 5;
        qoff_s[tid] = (h >= 0 && h < H1 && w >= 0 && w < W1) ? (h * W1 + w) * BB : -1;
    }
    __syncthreads();
    for (int t = tid; t < 400; t += NTHR) {
        int q = qoff_s[t >> 4];
        xn_s[t] = (q >= 0) ? g_xn[q + (t & 15)] : 0.f;
    }
    if (tid < 32) yn_s[tid] = g_yn[tile * NN + tid];

    // warp's valid slots (warp-uniform): up to 4
    int sp[4];
    int nsl = 0;
#pragma unroll
    for (int p = wid; p < 25; p += NWARP)
        if (qoff_s[p] >= 0) sp[nsl++] = p;

    float acc[4][4][4];
#pragma unroll
    for (int a = 0; a < 4; a++)
#pragma unroll
        for (int b = 0; b < 4; b++)
#pragma unroll
            for (int c = 0; c < 4; c++) acc[a][b][c] = 0.f;

    // ldmatrix per-lane byte offsets (within a stage buffer)
    //  A (.x4): lanes 0-7 rows0-7 k0 | 8-15 rows8-15 k0 | 16-23 rows0-7 k8 | 24-31 rows8-15 k8
    const uint32_t aoff = (lane & 15) * 144 + (lane >> 4) * 16;
    //  B (.x4): lanes 0-7 n0-7 k0 | 8-15 n0-7 k8 | 16-23 n8-15 k0 | 24-31 n8-15 k8
    const uint32_t boff = ((lane & 7) + ((lane & 16) ? 8 : 0)) * 144 + ((lane & 8) ? 16 : 0);

    const uint4* EbV = (const uint4*)g_Eb;
    const uint4* MbV = (const uint4*)g_Mb + (size_t)tile * (NN * CC / 8);

    // ---- async tile loader (one KC=64 chunk into staging buffer) ----
    auto load_stage = [&](int kc, int buf) {
        uint32_t abase = smA_u32 + buf * A_STAGE_B;
        for (int i = tid; i < 3200; i += NTHR) {
            int row = i >> 3, seg = i & 7;
            int q = qoff_s[row >> 4];
            if (q >= 0) {
                cp_async16(abase + row * 144 + seg * 16,
                           EbV + ((size_t)(q + (row & 15)) * CC + kc * KC) / 8 + seg);
            }
        }
        {
            int row = tid >> 3, seg = tid & 7;
            cp_async16(smB_u32 + buf * B_STAGE_B + row * 144 + seg * 16,
                       MbV + row * 64 + kc * 8 + seg);
        }
        asm volatile("cp.async.commit_group;");
    };

    // prologue: prefetch stages 0 and 1
    load_stage(0, 0);
    load_stage(1, 1);

    for (int kc = 0; kc < CC / KC; kc++) {
        if (kc < CC / KC - 1)
            asm volatile("cp.async.wait_group 1;");
        else
            asm volatile("cp.async.wait_group 0;");
        __syncthreads();

        const int buf = kc & 1;
        const uint32_t abase = smA_u32 + buf * A_STAGE_B;
        const uint32_t bbase = smB_u32 + buf * B_STAGE_B;

#pragma unroll
        for (int ks = 0; ks < 4; ks++) {
            const uint32_t kbyte = ks * 32;
            // B frags: n0-15 then n16-31  (b[t][0..1] = nb=2t ; b[t][2..3] = nb=2t+1)
            uint32_t b[2][4];
            ldsm_x4(b[0][0], b[0][1], b[0][2], b[0][3], bbase + boff + kbyte);
            ldsm_x4(b[1][0], b[1][1], b[1][2], b[1][3], bbase + boff + 16 * 144 + kbyte);
#pragma unroll
            for (int si = 0; si < 4; si++) {
                if (si < nsl) {
                    uint32_t a0, a1, a2, a3;
                    ldsm_x4(a0, a1, a2, a3, abase + sp[si] * 2304 + aoff + kbyte);
                    mma16816(acc[si][0], a0, a1, a2, a3, b[0][0], b[0][1]);
                    mma16816(acc[si][1], a0, a1, a2, a3, b[0][2], b[0][3]);
                    mma16816(acc[si][2], a0, a1, a2, a3, b[1][0], b[1][1]);
                    mma16816(acc[si][3], a0, a1, a2, a3, b[1][2], b[1][3]);
                }
            }
        }
        __syncthreads();   // all warps done reading buf before refill
        if (kc + 2 < CC / KC) load_stage(kc + 2, buf);
    }

    // epilogue: dsq = xn - 2*cross + yn ; min over n ; atomicMin into best
#pragma unroll
    for (int si = 0; si < 4; si++) {
        if (si < nsl) {
            int p = sp[si];
            float xlo = xn_s[p * 16 + (lane >> 2)];
            float xhi = xn_s[p * 16 + 8 + (lane >> 2)];
            float mlo = 3.4e38f, mhi = 3.4e38f;
#pragma unroll
            for (int nb = 0; nb < 4; nb++) {
                int c0 = nb * 8 + ((lane & 3) << 1);
                float y0 = yn_s[c0], y1 = yn_s[c0 + 1];
                mlo = fminf(mlo, fminf(fmaf(-2.f, acc[si][nb][0], xlo) + y0,
                                       fmaf(-2.f, acc[si][nb][1], xlo) + y1));
                mhi = fminf(mhi, fminf(fmaf(-2.f, acc[si][nb][2], xhi) + y0,
                                       fmaf(-2.f, acc[si][nb][3], xhi) + y1));
            }
            mlo = fminf(mlo, __shfl_xor_sync(~0u, mlo, 1));
            mlo = fminf(mlo, __shfl_xor_sync(~0u, mlo, 2));
            mhi = fminf(mhi, __shfl_xor_sync(~0u, mhi, 1));
            mhi = fminf(mhi, __shfl_xor_sync(~0u, mhi, 2));
            if ((lane & 3) == 0) {
                int q = qoff_s[p];
                atomicMin((int*)&g_best[q + (lane >> 2)], __float_as_int(fmaxf(mlo, 0.f)));
                atomicMin((int*)&g_best[q + 8 + (lane >> 2)], __float_as_int(fmaxf(mhi, 0.f)));
            }
        }
    }
}

// ---------------- sqrt + per-b max (img) + pix56 ---------------------------
__global__ void k_finish(float* __restrict__ out) {
    __shared__ float red[256];
    int b = blockIdx.x, tid = threadIdx.x;
    float mx = 0.f;
    for (int i = tid; i < H1 * W1; i += 256) {
        float v = sqrtf(g_best[i * BB + b]);
        g_pix56[b * H1 * W1 + i] = v;
        mx = fmaxf(mx, v);
    }
    red[tid] = mx;
    __syncthreads();
    for (int o = 128; o; o >>= 1) {
        if (tid < o) red[tid] = fmaxf(red[tid], red[tid + o]);
        __syncthreads();
    }
    if (tid == 0) out[b] = red[0];
}

// ---------------- bilinear 56 -> 224 (jax half-pixel, renorm == clamp) -----
__global__ void k_resize() {
    int idx = blockIdx.x * blockDim.x + threadIdx.x;
    if (idx >= BB * OH * OW) return;
    int b = idx / (OH * OW);
    int rm = idx % (OH * OW);
    int oy = rm / OW, ox = rm % OW;

    float uy = fminf(fmaxf((oy + 0.5f) * 0.25f - 0.5f, 0.f), 55.f);
    float ux = fminf(fmaxf((ox + 0.5f) * 0.25f - 0.5f, 0.f), 55.f);
    int y0 = (int)uy, x0 = (int)ux;
    float fy = uy - y0, fx = ux - x0;
    int y1 = min(y0 + 1, H1 - 1), x1 = min(x0 + 1, W1 - 1);

    const float* p = g_pix56 + b * H1 * W1;
    float v00 = p[y0 * W1 + x0], v01 = p[y0 * W1 + x1];
    float v10 = p[y1 * W1 + x0], v11 = p[y1 * W1 + x1];
    float v = (1.f - fy) * ((1.f - fx) * v00 + fx * v01) +
              fy * ((1.f - fx) * v10 + fx * v11);
    g_pix224[idx] = v;
}

// ---------------- separable gaussian blur, reflect padding -----------------
__device__ __forceinline__ int refl(int i) {
    return i < 0 ? -i : (i > 223 ? 446 - i : i);
}

__global__ void k_vblur() {
    int idx = blockIdx.x * blockDim.x + threadIdx.x;
    if (idx >= BB * OH * OW) return;
    int b = idx / (OH * OW);
    int rm = idx % (OH * OW);
    int y = rm / OW, x = rm % OW;
    const float* p = g_pix224 + b * OH * OW;
    float sum = 0.f;
#pragma unroll
    for (int t = 0; t < KS; t++) {
        int yy = refl(y + t - 16);
        sum += g_gw[t] * p[yy * OW + x];
    }
    g_tmp224[idx] = sum;
}

__global__ void k_hblur(float* __restrict__ out) {
    int idx = blockIdx.x * blockDim.x + threadIdx.x;
    if (idx >= BB * OH * OW) return;
    int b = idx / (OH * OW);
    int rm = idx % (OH * OW);
    int y = rm / OW, x = rm % OW;
    const float* p = g_tmp224 + b * OH * OW;
    float sum = 0.f;
#pragma unroll
    for (int t = 0; t < KS; t++) {
        int xx = refl(x + t - 16);
        sum += g_gw[t] * p[y * OW + xx];
    }
    out[idx] = sum;
}

// ---------------- launch ----------------------------------------------------
extern "C" void kernel_launch(void* const* d_in, const int* in_sizes, int n_in,
                              void* d_out, int out_size) {
    const float* emb = (const float*)d_in[0];
    const float* mem = (const float*)d_in[1];
    float* out = (float*)d_out;

    cudaFuncSetAttribute(k_dist, cudaFuncAttributeMaxDynamicSharedMemorySize, SM_TOT);

    k_init<<<(H1 * W1 * BB + 255) / 256, 256>>>();
    k_convert_e<<<(H1 * W1 * BB + 7) / 8, 256>>>(emb);
    k_convert_m<<<(RH * RW * NN + 7) / 8, 256>>>(mem);
    k_dist<<<RH * RW, NTHR, SM_TOT>>>();
    k_finish<<<BB, 256>>>(out);                       // writes img -> out[0..15]
    int nt = BB * OH * OW;
    k_resize<<<(nt + 255) / 256, 256>>>();
    k_vblur<<<(nt + 255) / 256, 256>>>();
    k_hblur<<<(nt + 255) / 256, 256>>>(out + BB);     // blur -> out[16..]
}

// round 5
// speedup vs baseline: 1.0885x; 1.0885x over previous
#include <cuda_runtime.h>
#include <cuda_bf16.h>
#include <cstdint>
#include <math.h>

#define H1 56
#define W1 56
#define BB 16
#define NN 32
#define CC 512
#define RH 60
#define RW 60
#define OH 224
#define OW 224
#define KS 33
#define KC 64
#define APITCH 72   // bf16 elements per smem row (64 data + 8 pad) ; 144 B

// ---------------- scratch (device globals; no allocation allowed) ----------
__device__ __nv_bfloat16 g_Eb[H1 * W1 * BB * CC];     // 51.4 MB
__device__ __nv_bfloat16 g_Mb[RH * RW * NN * CC];     // 118 MB
__device__ float g_xn[H1 * W1 * BB];
__device__ float g_yn[RH * RW * NN];
__device__ float g_best[H1 * W1 * BB];                // min dsq, via atomicMin(int)
__device__ float g_pix56[BB * H1 * W1];
__device__ float g_pix224[BB * OH * OW];
__device__ float g_tmp224[BB * OH * OW];
__device__ float g_gw[KS];

// ---------------- init: best=+inf, gaussian weights ------------------------
__global__ void k_init() {
    int i = blockIdx.x * blockDim.x + threadIdx.x;
    if (i < H1 * W1 * BB) g_best[i] = __int_as_float(0x7f800000);
    if (i < KS) {
        float s = 0.f;
        for (int t = 0; t < KS; t++) {
            float x = (t - (KS - 1) / 2) * 0.25f;   // /sigma=4
            s += expf(-0.5f * x * x);
        }
        float x = (i - (KS - 1) / 2) * 0.25f;
        g_gw[i] = expf(-0.5f * x * x) / s;
    }
}

// ---------------- fp32 -> bf16 conversion + row norms ----------------------
__device__ __forceinline__ void convert_row(const float* __restrict__ src,
                                            __nv_bfloat16* dst, float* norm,
                                            int row, int lane) {
    const float4* s = (const float4*)(src + (size_t)row * CC);
    uint2* d = (uint2*)(dst + (size_t)row * CC);
    float acc = 0.f;
#pragma unroll
    for (int it = 0; it < 4; it++) {
        float4 v = s[it * 32 + lane];
        acc += v.x * v.x + v.y * v.y + v.z * v.z + v.w * v.w;
        __nv_bfloat162 lo = __floats2bfloat162_rn(v.x, v.y);
        __nv_bfloat162 hi = __floats2bfloat162_rn(v.z, v.w);
        uint2 o;
        o.x = *(uint32_t*)&lo;
        o.y = *(uint32_t*)&hi;
        d[it * 32 + lane] = o;
    }
#pragma unroll
    for (int off = 16; off; off >>= 1) acc += __shfl_xor_sync(~0u, acc, off);
    if (lane == 0) norm[row] = acc;
}

__global__ void k_convert_e(const float* __restrict__ src) {
    int gw = (blockIdx.x * blockDim.x + threadIdx.x) >> 5;
    int lane = threadIdx.x & 31;
    if (gw < H1 * W1 * BB) convert_row(src, g_Eb, g_xn, gw, lane);
}
__global__ void k_convert_m(const float* __restrict__ src) {
    int gw = (blockIdx.x * blockDim.x + threadIdx.x) >> 5;
    int lane = threadIdx.x & 31;
    if (gw < RH * RW * NN) convert_row(src, g_Mb, g_yn, gw, lane);
}

// ---------------- main distance kernel: one CTA per memory tile ------------
__device__ __forceinline__ void mma16816(float* d, uint32_t a0, uint32_t a1,
                                         uint32_t a2, uint32_t a3,
                                         uint32_t b0, uint32_t b1) {
    asm volatile(
        "mma.sync.aligned.m16n8k16.row.col.f32.bf16.bf16.f32 "
        "{%0,%1,%2,%3}, {%4,%5,%6,%7}, {%8,%9}, {%0,%1,%2,%3};\n"
        : "+f"(d[0]), "+f"(d[1]), "+f"(d[2]), "+f"(d[3])
        : "r"(a0), "r"(a1), "r"(a2), "r"(a3), "r"(b0), "r"(b1));
}

__device__ __forceinline__ void ldsm_x4(uint32_t& r0, uint32_t& r1,
                                        uint32_t& r2, uint32_t& r3, uint32_t addr) {
    asm volatile("ldmatrix.sync.aligned.m8n8.x4.shared.b16 {%0,%1,%2,%3}, [%4];"
                 : "=r"(r0), "=r"(r1), "=r"(r2), "=r"(r3) : "r"(addr));
}

__device__ __forceinline__ void cp_async16(uint32_t dst, const void* src) {
    asm volatile("cp.async.cg.shared.global [%0], [%1], 16;" ::"r"(dst), "l"(src));
}

// smem layout (bytes):
//   A_s : 2 stages x 400*72*2 = 115200
//   B_s : 2 stages x 32*72*2  = 9216
//   xn_s: 400*4 = 1600 ; yn_s: 128 ; qoff: 100
#define A_STAGE_B 57600
#define B_STAGE_B 4608
#define SM_A   0
#define SM_B   115200
#define SM_XN  124416
#define SM_YN  126016
#define SM_Q   126144
#define SM_TOT 126272

#define NWARP 16
#define NTHR  512

__global__ void __launch_bounds__(NTHR, 1) k_dist() {
    extern __shared__ char smem[];
    float* xn_s = (float*)(smem + SM_XN);
    float* yn_s = (float*)(smem + SM_YN);
    int* qoff_s = (int*)(smem + SM_Q);
    const uint32_t sm_u32 = (uint32_t)__cvta_generic_to_shared(smem);
    const uint32_t smA_u32 = sm_u32 + SM_A;
    const uint32_t smB_u32 = sm_u32 + SM_B;

    const int tile = blockIdx.x;
    const int r = tile / RW, s = tile % RW;
    const int tid = threadIdx.x;
    const int wid = tid >> 5, lane = tid & 31;

    if (tid < 25) {
        int h = r - 4 + tid / 5, w = s - 4 + tid % 5;
        qoff_s[tid] = (h >= 0 && h < H1 && w >= 0 && w < W1) ? (h * W1 + w) * BB : -1;
    }
    __syncthreads();
    for (int t = tid; t < 400; t += NTHR) {
        int q = qoff_s[t >> 4];
        xn_s[t] = (q >= 0) ? g_xn[q + (t & 15)] : 0.f;
    }
    if (tid < 32) yn_s[tid] = g_yn[tile * NN + tid];

    // warp's valid slots (warp-uniform): up to 2 (16 warps cover 25 slots)
    int sp[2];
    int nsl = 0;
#pragma unroll
    for (int p = wid; p < 25; p += NWARP)
        if (qoff_s[p] >= 0) sp[nsl++] = p;

    float acc[2][4][4];
#pragma unroll
    for (int a = 0; a < 2; a++)
#pragma unroll
        for (int b = 0; b < 4; b++)
#pragma unroll
            for (int c = 0; c < 4; c++) acc[a][b][c] = 0.f;

    // ldmatrix per-lane byte offsets (within a stage buffer)
    //  A (.x4): lanes 0-7 rows0-7 k0 | 8-15 rows8-15 k0 | 16-23 rows0-7 k8 | 24-31 rows8-15 k8
    const uint32_t aoff = (lane & 15) * 144 + (lane >> 4) * 16;
    //  B (.x4): lanes 0-7 n0-7 k0 | 8-15 n0-7 k8 | 16-23 n8-15 k0 | 24-31 n8-15 k8
    const uint32_t boff = ((lane & 7) + ((lane & 16) ? 8 : 0)) * 144 + ((lane & 8) ? 16 : 0);

    const uint4* EbV = (const uint4*)g_Eb;
    const uint4* MbV = (const uint4*)g_Mb + (size_t)tile * (NN * CC / 8);

    // ---- async tile loader (one KC=64 chunk into staging buffer) ----
    auto load_stage = [&](int kc, int buf) {
        uint32_t abase = smA_u32 + buf * A_STAGE_B;
        for (int i = tid; i < 3200; i += NTHR) {
            int row = i >> 3, seg = i & 7;
            int q = qoff_s[row >> 4];
            if (q >= 0) {
                cp_async16(abase + row * 144 + seg * 16,
                           EbV + ((size_t)(q + (row & 15)) * CC + kc * KC) / 8 + seg);
            }
        }
        if (tid < 256) {
            int row = tid >> 3, seg = tid & 7;
            cp_async16(smB_u32 + buf * B_STAGE_B + row * 144 + seg * 16,
                       MbV + row * 64 + kc * 8 + seg);
        }
        asm volatile("cp.async.commit_group;");
    };

    // prologue: prefetch stages 0 and 1
    load_stage(0, 0);
    load_stage(1, 1);

    for (int kc = 0; kc < CC / KC; kc++) {
        if (kc < CC / KC - 1)
            asm volatile("cp.async.wait_group 1;");
        else
            asm volatile("cp.async.wait_group 0;");
        __syncthreads();

        const int buf = kc & 1;
        const uint32_t abase = smA_u32 + buf * A_STAGE_B;
        const uint32_t bbase = smB_u32 + buf * B_STAGE_B;

#pragma unroll
        for (int ks = 0; ks < 4; ks++) {
            const uint32_t kbyte = ks * 32;
            // B frags: n0-15 then n16-31  (b[t][0..1] = nb=2t ; b[t][2..3] = nb=2t+1)
            uint32_t b[2][4];
            ldsm_x4(b[0][0], b[0][1], b[0][2], b[0][3], bbase + boff + kbyte);
            ldsm_x4(b[1][0], b[1][1], b[1][2], b[1][3], bbase + boff + 16 * 144 + kbyte);
#pragma unroll
            for (int si = 0; si < 2; si++) {
                if (si < nsl) {
                    uint32_t a0, a1, a2, a3;
                    ldsm_x4(a0, a1, a2, a3, abase + sp[si] * 2304 + aoff + kbyte);
                    mma16816(acc[si][0], a0, a1, a2, a3, b[0][0], b[0][1]);
                    mma16816(acc[si][1], a0, a1, a2, a3, b[0][2], b[0][3]);
                    mma16816(acc[si][2], a0, a1, a2, a3, b[1][0], b[1][1]);
                    mma16816(acc[si][3], a0, a1, a2, a3, b[1][2], b[1][3]);
                }
            }
        }
        __syncthreads();   // all warps done reading buf before refill
        if (kc + 2 < CC / KC) load_stage(kc + 2, buf);
    }

    // epilogue: dsq = xn - 2*cross + yn ; min over n ; atomicMin into best
#pragma unroll
    for (int si = 0; si < 2; si++) {
        if (si < nsl) {
            int p = sp[si];
            float xlo = xn_s[p * 16 + (lane >> 2)];
            float xhi = xn_s[p * 16 + 8 + (lane >> 2)];
            float mlo = 3.4e38f, mhi = 3.4e38f;
#pragma unroll
            for (int nb = 0; nb < 4; nb++) {
                int c0 = nb * 8 + ((lane & 3) << 1);
                float y0 = yn_s[c0], y1 = yn_s[c0 + 1];
                mlo = fminf(mlo, fminf(fmaf(-2.f, acc[si][nb][0], xlo) + y0,
                                       fmaf(-2.f, acc[si][nb][1], xlo) + y1));
                mhi = fminf(mhi, fminf(fmaf(-2.f, acc[si][nb][2], xhi) + y0,
                                       fmaf(-2.f, acc[si][nb][3], xhi) + y1));
            }
            mlo = fminf(mlo, __shfl_xor_sync(~0u, mlo, 1));
            mlo = fminf(mlo, __shfl_xor_sync(~0u, mlo, 2));
            mhi = fminf(mhi, __shfl_xor_sync(~0u, mhi, 1));
            mhi = fminf(mhi, __shfl_xor_sync(~0u, mhi, 2));
            if ((lane & 3) == 0) {
                int q = qoff_s[p];
                atomicMin((int*)&g_best[q + (lane >> 2)], __float_as_int(fmaxf(mlo, 0.f)));
                atomicMin((int*)&g_best[q + 8 + (lane >> 2)], __float_as_int(fmaxf(mhi, 0.f)));
            }
        }
    }
}

// ---------------- sqrt + per-b max (img) + pix56 ---------------------------
__global__ void k_finish(float* __restrict__ out) {
    __shared__ float red[256];
    int b = blockIdx.x, tid = threadIdx.x;
    float mx = 0.f;
    for (int i = tid; i < H1 * W1; i += 256) {
        float v = sqrtf(g_best[i * BB + b]);
        g_pix56[b * H1 * W1 + i] = v;
        mx = fmaxf(mx, v);
    }
    red[tid] = mx;
    __syncthreads();
    for (int o = 128; o; o >>= 1) {
        if (tid < o) red[tid] = fmaxf(red[tid], red[tid + o]);
        __syncthreads();
    }
    if (tid == 0) out[b] = red[0];
}

// ---------------- bilinear 56 -> 224 (jax half-pixel, renorm == clamp) -----
__global__ void k_resize() {
    int idx = blockIdx.x * blockDim.x + threadIdx.x;
    if (idx >= BB * OH * OW) return;
    int b = idx / (OH * OW);
    int rm = idx % (OH * OW);
    int oy = rm / OW, ox = rm % OW;

    float uy = fminf(fmaxf((oy + 0.5f) * 0.25f - 0.5f, 0.f), 55.f);
    float ux = fminf(fmaxf((ox + 0.5f) * 0.25f - 0.5f, 0.f), 55.f);
    int y0 = (int)uy, x0 = (int)ux;
    float fy = uy - y0, fx = ux - x0;
    int y1 = min(y0 + 1, H1 - 1), x1 = min(x0 + 1, W1 - 1);

    const float* p = g_pix56 + b * H1 * W1;
    float v00 = p[y0 * W1 + x0], v01 = p[y0 * W1 + x1];
    float v10 = p[y1 * W1 + x0], v11 = p[y1 * W1 + x1];
    float v = (1.f - fy) * ((1.f - fx) * v00 + fx * v01) +
              fy * ((1.f - fx) * v10 + fx * v11);
    g_pix224[idx] = v;
}

// ---------------- separable gaussian blur, reflect padding -----------------
__device__ __forceinline__ int refl(int i) {
    return i < 0 ? -i : (i > 223 ? 446 - i : i);
}

__global__ void k_vblur() {
    int idx = blockIdx.x * blockDim.x + threadIdx.x;
    if (idx >= BB * OH * OW) return;
    int b = idx / (OH * OW);
    int rm = idx % (OH * OW);
    int y = rm / OW, x = rm % OW;
    const float* p = g_pix224 + b * OH * OW;
    float sum = 0.f;
#pragma unroll
    for (int t = 0; t < KS; t++) {
        int yy = refl(y + t - 16);
        sum += g_gw[t] * p[yy * OW + x];
    }
    g_tmp224[idx] = sum;
}

__global__ void k_hblur(float* __restrict__ out) {
    int idx = blockIdx.x * blockDim.x + threadIdx.x;
    if (idx >= BB * OH * OW) return;
    int b = idx / (OH * OW);
    int rm = idx % (OH * OW);
    int y = rm / OW, x = rm % OW;
    const float* p = g_tmp224 + b * OH * OW;
    float sum = 0.f;
#pragma unroll
    for (int t = 0; t < KS; t++) {
        int xx = refl(x + t - 16);
        sum += g_gw[t] * p[y * OW + xx];
    }
    out[idx] = sum;
}

// ---------------- launch ----------------------------------------------------
extern "C" void kernel_launch(void* const* d_in, const int* in_sizes, int n_in,
                              void* d_out, int out_size) {
    const float* emb = (const float*)d_in[0];
    const float* mem = (const float*)d_in[1];
    float* out = (float*)d_out;

    cudaFuncSetAttribute(k_dist, cudaFuncAttributeMaxDynamicSharedMemorySize, SM_TOT);

    k_init<<<(H1 * W1 * BB + 255) / 256, 256>>>();
    k_convert_e<<<(H1 * W1 * BB + 7) / 8, 256>>>(emb);
    k_convert_m<<<(RH * RW * NN + 7) / 8, 256>>>(mem);
    k_dist<<<RH * RW, NTHR, SM_TOT>>>();
    k_finish<<<BB, 256>>>(out);                       // writes img -> out[0..15]
    int nt = BB * OH * OW;
    k_resize<<<(nt + 255) / 256, 256>>>();
    k_vblur<<<(nt + 255) / 256, 256>>>();
    k_hblur<<<(nt + 255) / 256, 256>>>(out + BB);     // blur -> out[16..]
}

// round 7
// speedup vs baseline: 1.3688x; 1.2574x over previous
#include <cuda_runtime.h>
#include <cuda_bf16.h>
#include <cstdint>
#include <math.h>

#define H1 56
#define W1 56
#define BB 16
#define NN 32
#define CC 512
#define RH 60
#define RW 60
#define OH 224
#define OW 224
#define KS 33
#define KC 64

// ---------------- scratch (device globals; no allocation allowed) ----------
__device__ __nv_bfloat16 g_Eb[H1 * W1 * BB * CC];     // 51.4 MB
__device__ __nv_bfloat16 g_Mb[RH * RW * NN * CC];     // 118 MB
__device__ float g_xn[H1 * W1 * BB];
__device__ float g_yn[RH * RW * NN];
__device__ float g_best[H1 * W1 * BB];                // min dsq, via atomicMin(int)
__device__ float g_pix56[BB * H1 * W1];
__device__ float g_pix224[BB * OH * OW];
__device__ float g_tmp224[BB * OH * OW];
__device__ float g_gw[KS];

// ---------------- init ------------------------------------------------------
__global__ void k_init() {
    int i = blockIdx.x * blockDim.x + threadIdx.x;
    if (i < H1 * W1 * BB) g_best[i] = __int_as_float(0x7f800000);
    if (i < KS) {
        float s = 0.f;
        for (int t = 0; t < KS; t++) {
            float x = (t - (KS - 1) / 2) * 0.25f;
            s += expf(-0.5f * x * x);
        }
        float x = (i - (KS - 1) / 2) * 0.25f;
        g_gw[i] = expf(-0.5f * x * x) / s;
    }
}

// ---------------- fp32 -> bf16 conversion + row norms ----------------------
__device__ __forceinline__ void convert_row(const float* __restrict__ src,
                                            __nv_bfloat16* dst, float* norm,
                                            int row, int lane) {
    const float4* s = (const float4*)(src + (size_t)row * CC);
    uint2* d = (uint2*)(dst + (size_t)row * CC);
    float acc = 0.f;
#pragma unroll
    for (int it = 0; it < 4; it++) {
        float4 v = s[it * 32 + lane];
        acc += v.x * v.x + v.y * v.y + v.z * v.z + v.w * v.w;
        __nv_bfloat162 lo = __floats2bfloat162_rn(v.x, v.y);
        __nv_bfloat162 hi = __floats2bfloat162_rn(v.z, v.w);
        uint2 o;
        o.x = *(uint32_t*)&lo;
        o.y = *(uint32_t*)&hi;
        d[it * 32 + lane] = o;
    }
#pragma unroll
    for (int off = 16; off; off >>= 1) acc += __shfl_xor_sync(~0u, acc, off);
    if (lane == 0) norm[row] = acc;
}

__global__ void k_convert_e(const float* __restrict__ src) {
    int gw = (blockIdx.x * blockDim.x + threadIdx.x) >> 5;
    int lane = threadIdx.x & 31;
    if (gw < H1 * W1 * BB) convert_row(src, g_Eb, g_xn, gw, lane);
}
__global__ void k_convert_m(const float* __restrict__ src) {
    int gw = (blockIdx.x * blockDim.x + threadIdx.x) >> 5;
    int lane = threadIdx.x & 31;
    if (gw < RH * RW * NN) convert_row(src, g_Mb, g_yn, gw, lane);
}

// ---------------- main distance kernel --------------------------------------
__device__ __forceinline__ void mma16816(float* d, uint32_t a0, uint32_t a1,
                                         uint32_t a2, uint32_t a3,
                                         uint32_t b0, uint32_t b1) {
    asm volatile(
        "mma.sync.aligned.m16n8k16.row.col.f32.bf16.bf16.f32 "
        "{%0,%1,%2,%3}, {%4,%5,%6,%7}, {%8,%9}, {%0,%1,%2,%3};\n"
        : "+f"(d[0]), "+f"(d[1]), "+f"(d[2]), "+f"(d[3])
        : "r"(a0), "r"(a1), "r"(a2), "r"(a3), "r"(b0), "r"(b1));
}

__device__ __forceinline__ void ldsm_x4(uint32_t& r0, uint32_t& r1,
                                        uint32_t& r2, uint32_t& r3, uint32_t addr) {
    asm volatile("ldmatrix.sync.aligned.m8n8.x4.shared.b16 {%0,%1,%2,%3}, [%4];"
                 : "=r"(r0), "=r"(r1), "=r"(r2), "=r"(r3) : "r"(addr));
}

__device__ __forceinline__ void cp_async16(uint32_t dst, const void* src) {
    asm volatile("cp.async.cg.shared.global [%0], [%1], 16;" ::"r"(dst), "l"(src));
}

__device__ __forceinline__ uint32_t sw128(uint32_t off) {
    return off ^ ((off >> 3) & 0x70);
}

// smem layout (bytes), 128B rows + SW128 swizzle (no padding):
//   A: 2 stages x 400 rows x 128B = 102400
//   B: 2 stages x  32 rows x 128B =   8192
#define A_STAGE_B 51200
#define B_STAGE_B 4096
#define SM_A   0
#define SM_B   102400
#define SM_XN  110592
#define SM_YN  112192
#define SM_Q   112320
#define SM_TOT 112512

#define NWARP 16
#define NTHR  512

__global__ void __launch_bounds__(NTHR, 2) k_dist() {
    extern __shared__ char smem[];
    float* xn_s = (float*)(smem + SM_XN);
    float* yn_s = (float*)(smem + SM_YN);
    int* qoff_s = (int*)(smem + SM_Q);
    const uint32_t sm_u32 = (uint32_t)__cvta_generic_to_shared(smem);
    const uint32_t smA_u32 = sm_u32 + SM_A;
    const uint32_t smB_u32 = sm_u32 + SM_B;

    const int tile = blockIdx.x;
    const int r = tile / RW, s = tile % RW;
    const int tid = threadIdx.x;
    const int wid = tid >> 5, lane = tid & 31;

    if (tid < 25) {
        int h = r - 4 + tid / 5, w = s - 4 + tid % 5;
        qoff_s[tid] = (h >= 0 && h < H1 && w >= 0 && w < W1) ? (h * W1 + w) * BB : -1;
    }
    __syncthreads();
    for (int t = tid; t < 400; t += NTHR) {
        int q = qoff_s[t >> 4];
        xn_s[t] = (q >= 0) ? g_xn[q + (t & 15)] : 0.f;
    }
    if (tid < 32) yn_s[tid] = g_yn[tile * NN + tid];

    // warp's valid slots (warp-uniform): up to 2 (16 warps cover 25 slots)
    int sp[2];
    int nsl = 0;
#pragma unroll
    for (int p = wid; p < 25; p += NWARP)
        if (qoff_s[p] >= 0) sp[nsl++] = p;

    float acc[2][4][4];
#pragma unroll
    for (int a = 0; a < 2; a++)
#pragma unroll
        for (int b = 0; b < 4; b++)
#pragma unroll
            for (int c = 0; c < 4; c++) acc[a][b][c] = 0.f;

    // ldmatrix lane geometry (swizzled 128B rows)
    //  A (.x4): row-within-slot = lane&15 ; k half (0/16B) = lane>>4
    const uint32_t arow = lane & 15;
    const uint32_t arow128 = arow * 128;
    const uint32_t axor = (arow & 7) << 4;
    const uint32_t akse = (lane >> 4) * 16;           // 0 or 16
    //  B (.x4): n row = (lane&7) + (lane&16 ? 8:0) ; k half = (lane&8 ? 16:0)
    const uint32_t brow = (lane & 7) + ((lane & 16) ? 8 : 0);
    const uint32_t brow128 = brow * 128;
    const uint32_t bxor = (brow & 7) << 4;
    const uint32_t bkse = (lane & 8) ? 16 : 0;

    const uint4* EbV = (const uint4*)g_Eb;
    const uint4* MbV = (const uint4*)g_Mb + (size_t)tile * (NN * CC / 8);

    // ---- async tile loader (one KC=64 chunk into staging buffer) ----
    auto load_stage = [&](int kc, int buf) {
        uint32_t abase = smA_u32 + buf * A_STAGE_B;
        for (int i = tid; i < 3200; i += NTHR) {
            int row = i >> 3, seg = i & 7;
            int q = qoff_s[row >> 4];
            if (q >= 0) {
                cp_async16(abase + sw128(row * 128 + seg * 16),
                           EbV + ((size_t)(q + (row & 15)) * CC + kc * KC) / 8 + seg);
            }
        }
        if (tid < 256) {
            int row = tid >> 3, seg = tid & 7;
            cp_async16(smB_u32 + buf * B_STAGE_B + sw128(row * 128 + seg * 16),
                       MbV + row * 64 + kc * 8 + seg);
        }
        asm volatile("cp.async.commit_group;");
    };

    // prologue: prefetch stages 0 and 1
    load_stage(0, 0);
    load_stage(1, 1);

    for (int kc = 0; kc < CC / KC; kc++) {
        if (kc < CC / KC - 1)
            asm volatile("cp.async.wait_group 1;");
        else
            asm volatile("cp.async.wait_group 0;");
        __syncthreads();

        const int buf = kc & 1;
        const uint32_t abase = smA_u32 + buf * A_STAGE_B;
        const uint32_t bbase = smB_u32 + buf * B_STAGE_B;

#pragma unroll
        for (int ks = 0; ks < 4; ks++) {
            const uint32_t kbyte = ks * 32;
            // B frags: n0-15 then n16-31
            uint32_t b[2][4];
            const uint32_t baddr = bbase + brow128 + ((bkse + kbyte) ^ bxor);
            ldsm_x4(b[0][0], b[0][1], b[0][2], b[0][3], baddr);
            ldsm_x4(b[1][0], b[1][1], b[1][2], b[1][3], baddr + 16 * 128);
#pragma unroll
            for (int si = 0; si < 2; si++) {
                if (si < nsl) {
                    uint32_t a0, a1, a2, a3;
                    ldsm_x4(a0, a1, a2, a3,
                            abase + sp[si] * 2048 + arow128 + ((akse + kbyte) ^ axor));
                    mma16816(acc[si][0], a0, a1, a2, a3, b[0][0], b[0][1]);
                    mma16816(acc[si][1], a0, a1, a2, a3, b[0][2], b[0][3]);
                    mma16816(acc[si][2], a0, a1, a2, a3, b[1][0], b[1][1]);
                    mma16816(acc[si][3], a0, a1, a2, a3, b[1][2], b[1][3]);
                }
            }
        }
        __syncthreads();   // all warps done reading buf before refill
        if (kc + 2 < CC / KC) load_stage(kc + 2, buf);
    }

    // epilogue: dsq = xn - 2*cross + yn ; min over n ; atomicMin into best
#pragma unroll
    for (int si = 0; si < 2; si++) {
        if (si < nsl) {
            int p = sp[si];
            float xlo = xn_s[p * 16 + (lane >> 2)];
            float xhi = xn_s[p * 16 + 8 + (lane >> 2)];
            float mlo = 3.4e38f, mhi = 3.4e38f;
#pragma unroll
            for (int nb = 0; nb < 4; nb++) {
                int c0 = nb * 8 + ((lane & 3) << 1);
                float y0 = yn_s[c0], y1 = yn_s[c0 + 1];
                mlo = fminf(mlo, fminf(fmaf(-2.f, acc[si][nb][0], xlo) + y0,
                                       fmaf(-2.f, acc[si][nb][1], xlo) + y1));
                mhi = fminf(mhi, fminf(fmaf(-2.f, acc[si][nb][2], xhi) + y0,
                                       fmaf(-2.f, acc[si][nb][3], xhi) + y1));
            }
            mlo = fminf(mlo, __shfl_xor_sync(~0u, mlo, 1));
            mlo = fminf(mlo, __shfl_xor_sync(~0u, mlo, 2));
            mhi = fminf(mhi, __shfl_xor_sync(~0u, mhi, 1));
            mhi = fminf(mhi, __shfl_xor_sync(~0u, mhi, 2));
            if ((lane & 3) == 0) {
                int q = qoff_s[p];
                atomicMin((int*)&g_best[q + (lane >> 2)], __float_as_int(fmaxf(mlo, 0.f)));
                atomicMin((int*)&g_best[q + 8 + (lane >> 2)], __float_as_int(fmaxf(mhi, 0.f)));
            }
        }
    }
}

// ---------------- sqrt + per-b max (img) + pix56 ---------------------------
__global__ void k_finish(float* __restrict__ out) {
    __shared__ float red[256];
    int b = blockIdx.x, tid = threadIdx.x;
    float mx = 0.f;
    for (int i = tid; i < H1 * W1; i += 256) {
        float v = sqrtf(g_best[i * BB + b]);
        g_pix56[b * H1 * W1 + i] = v;
        mx = fmaxf(mx, v);
    }
    red[tid] = mx;
    __syncthreads();
    for (int o = 128; o; o >>= 1) {
        if (tid < o) red[tid] = fmaxf(red[tid], red[tid + o]);
        __syncthreads();
    }
    if (tid == 0) out[b] = red[0];
}

// ---------------- bilinear 56 -> 224 ----------------------------------------
__global__ void k_resize() {
    int idx = blockIdx.x * blockDim.x + threadIdx.x;
    if (idx >= BB * OH * OW) return;
    int b = idx / (OH * OW);
    int rm = idx % (OH * OW);
    int oy = rm / OW, ox = rm % OW;

    float uy = fminf(fmaxf((oy + 0.5f) * 0.25f - 0.5f, 0.f), 55.f);
    float ux = fminf(fmaxf((ox + 0.5f) * 0.25f - 0.5f, 0.f), 55.f);
    int y0 = (int)uy, x0 = (int)ux;
    float fy = uy - y0, fx = ux - x0;
    int y1 = min(y0 + 1, H1 - 1), x1 = min(x0 + 1, W1 - 1);

    const float* p = g_pix56 + b * H1 * W1;
    float v00 = p[y0 * W1 + x0], v01 = p[y0 * W1 + x1];
    float v10 = p[y1 * W1 + x0], v11 = p[y1 * W1 + x1];
    float v = (1.f - fy) * ((1.f - fx) * v00 + fx * v01) +
              fy * ((1.f - fx) * v10 + fx * v11);
    g_pix224[idx] = v;
}

// ---------------- separable gaussian blur, reflect padding ------------------
__device__ __forceinline__ int refl(int i) {
    return i < 0 ? -i : (i > 223 ? 446 - i : i);
}

__global__ void k_vblur() {
    int idx = blockIdx.x * blockDim.x + threadIdx.x;
    if (idx >= BB * OH * OW) return;
    int b = idx / (OH * OW);
    int rm = idx % (OH * OW);
    int y = rm / OW, x = rm % OW;
    const float* p = g_pix224 + b * OH * OW;
    float sum = 0.f;
#pragma unroll
    for (int t = 0; t < KS; t++) {
        int yy = refl(y + t - 16);
        sum += g_gw[t] * p[yy * OW + x];
    }
    g_tmp224[idx] = sum;
}

__global__ void k_hblur(float* __restrict__ out) {
    int idx = blockIdx.x * blockDim.x + threadIdx.x;
    if (idx >= BB * OH * OW) return;
    int b = idx / (OH * OW);
    int rm = idx % (OH * OW);
    int y = rm / OW, x = rm % OW;
    const float* p = g_tmp224 + b * OH * OW;
    float sum = 0.f;
#pragma unroll
    for (int t = 0; t < KS; t++) {
        int xx = refl(x + t - 16);
        sum += g_gw[t] * p[y * OW + xx];
    }
    out[idx] = sum;
}

// ---------------- launch ------------------------------------------------------
extern "C" void kernel_launch(void* const* d_in, const int* in_sizes, int n_in,
                              void* d_out, int out_size) {
    const float* emb = (const float*)d_in[0];
    const float* mem = (const float*)d_in[1];
    float* out = (float*)d_out;

    cudaFuncSetAttribute(k_dist, cudaFuncAttributeMaxDynamicSharedMemorySize, SM_TOT);

    k_init<<<(H1 * W1 * BB + 255) / 256, 256>>>();
    k_convert_e<<<(H1 * W1 * BB + 7) / 8, 256>>>(emb);
    k_convert_m<<<(RH * RW * NN + 7) / 8, 256>>>(mem);
    k_dist<<<RH * RW, NTHR, SM_TOT>>>();
    k_finish<<<BB, 256>>>(out);                       // img -> out[0..15]
    int nt = BB * OH * OW;
    k_resize<<<(nt + 255) / 256, 256>>>();
    k_vblur<<<(nt + 255) / 256, 256>>>();
    k_hblur<<<(nt + 255) / 256, 256>>>(out + BB);     // blur -> out[16..]
}